// round 4
// baseline (speedup 1.0000x reference)
#include <cuda_runtime.h>
#include <cuda_bf16.h>

// Comparator4Bit: A,B are (N,4) float32 with values in {0,1}.
// col0 = bit3 (MSB) ... col3 = bit0 (LSB).
// out[0:N] = (valA > valB) ? 1.0f : 0.0f;  out[N:2N] = (valA == valB) ? 1.0f : 0.0f
//
// HBM-bound streaming: 128 MiB read + 32 MiB write. Flat launch, 2 rows/thread,
// 8 CTAs/SM. Loads use __ldcg (L2-only; zero L1 reuse, cut l1tex work).
// Packing via uint shifts (0x3F800000 bit29 set iff 1.0f) — ALU only, no F2I.

static __device__ __forceinline__ int pack_row_u(const uint4 v) {
    // v.* is 0x00000000 (0.0f) or 0x3F800000 (1.0f); bit 29 distinguishes.
    return ((v.x >> 26) & 8u) | ((v.y >> 27) & 4u) |
           ((v.z >> 28) & 2u) | ((v.w >> 29) & 1u);
}

__global__ void __launch_bounds__(256, 8)
comparator4bit_kernel(const uint4* __restrict__ A4,
                      const uint4* __restrict__ B4,
                      float2* __restrict__ out_gt2,
                      float2* __restrict__ out_eq2,
                      int n_units)   // n_rows / 2 work units
{
    int t = blockIdx.x * blockDim.x + threadIdx.x;
    if (t >= n_units) return;
    int base = t * 2;

    // Front-batch all 4 loads (L2-only caching; single-touch data).
    uint4 a0 = __ldcg(A4 + base + 0);
    uint4 a1 = __ldcg(A4 + base + 1);
    uint4 b0 = __ldcg(B4 + base + 0);
    uint4 b1 = __ldcg(B4 + base + 1);

    int va0 = pack_row_u(a0), vb0 = pack_row_u(b0);
    int va1 = pack_row_u(a1), vb1 = pack_row_u(b1);

    float2 gt, eq;
    gt.x = (va0 > vb0) ? 1.0f : 0.0f;  eq.x = (va0 == vb0) ? 1.0f : 0.0f;
    gt.y = (va1 > vb1) ? 1.0f : 0.0f;  eq.y = (va1 == vb1) ? 1.0f : 0.0f;

    out_gt2[t] = gt;
    out_eq2[t] = eq;
}

extern "C" void kernel_launch(void* const* d_in, const int* in_sizes, int n_in,
                              void* d_out, int out_size) {
    const float* A = (const float*)d_in[0];
    const float* B = (const float*)d_in[1];
    float* out = (float*)d_out;

    int n_rows = in_sizes[0] / 4;   // (N,4) float32 -> N rows
    int n_units = n_rows / 2;       // 2 rows per thread

    float* out_gt = out;            // [0:N)
    float* out_eq = out + n_rows;   // [N:2N)

    const int threads = 256;
    int blocks = (n_units + threads - 1) / threads;

    comparator4bit_kernel<<<blocks, threads>>>(
        (const uint4*)A, (const uint4*)B,
        (float2*)out_gt, (float2*)out_eq, n_units);
}